// round 1
// baseline (speedup 1.0000x reference)
#include <cuda_runtime.h>
#include <math.h>

#define NCLS 20
#define NA 5
#define HH 26
#define WW 26
#define NLOC 3380      // NA*HH*WW
#define NPAD 4096
#define BATCH 16
#define NMS_TH 0.45f
#define PRE_TH 0.005f
#define FEAT_STRIDE 32.0f
#define NTHR 1024

__constant__ float c_biases[10] = {1.08f, 1.19f, 3.42f, 4.41f, 6.63f, 11.38f,
                                   9.42f, 5.11f, 16.62f, 10.52f};

struct Smem {
    float skey[NPAD];
    int   sidx[NPAD];
    float x1[NLOC], y1[NLOC], x2[NLOC], y2[NLOC], ar[NLOC];
    unsigned kw[NPAD / 32];
    int npos;
    int nexti;
};

extern __shared__ char smem_raw[];

__global__ void __launch_bounds__(NTHR, 1)
yolo_kernel(const float* __restrict__ x, const float* __restrict__ im_info,
            float* __restrict__ out)
{
    Smem* s = reinterpret_cast<Smem*>(smem_raw);
    const int b = blockIdx.x;
    const int tid = threadIdx.x;

    const float im_h = im_info[0];
    const float im_w = im_info[1];
    const float netw = WW * FEAT_STRIDE;
    const float neth = HH * FEAT_STRIDE;
    const bool cond = (netw / im_w) < (neth / im_h);
    const float new_w = cond ? netw : im_w * neth / im_h;
    const float new_h = cond ? im_h * netw / im_w : neth;

    float* prob = out;                                    // (B, NLOC, 21)
    float* bbox = out + (size_t)BATCH * NLOC * 21;        // (B, NLOC, 4)
    const float* xb = x + (size_t)b * 125 * (HH * WW);

    // ---- phase 1: decode ----
    for (int loc = tid; loc < NLOC; loc += NTHR) {
        int a = loc / (HH * WW);
        int rem = loc - a * (HH * WW);
        int hh = rem / WW;
        int ww = rem - hh * WW;

        float tx = xb[(2 * a) * 676 + rem];
        float ty = xb[(2 * a + 1) * 676 + rem];
        float tw = xb[(10 + 2 * a) * 676 + rem];
        float th = xb[(11 + 2 * a) * 676 + rem];
        float to = xb[(20 + a) * 676 + rem];

        float obj = 1.0f / (1.0f + expf(-to));

        // softmax over 20 classes
        float cf[NCLS];
        float m = -INFINITY;
#pragma unroll
        for (int c = 0; c < NCLS; c++) {
            cf[c] = xb[(25 + 5 * c + a) * 676 + rem];
            m = fmaxf(m, cf[c]);
        }
        float sum = 0.0f;
#pragma unroll
        for (int c = 0; c < NCLS; c++) {
            cf[c] = expf(cf[c] - m);
            sum += cf[c];
        }
        float inv = obj / sum;
        float* pr = prob + ((size_t)b * NLOC + loc) * 21;
#pragma unroll
        for (int c = 0; c < NCLS; c++) pr[c] = cf[c] * inv;

        // box decode
        float sx = 1.0f / (1.0f + expf(-tx));
        float sy = 1.0f / (1.0f + expf(-ty));
        float bxv = ((float)ww + sx) / (float)WW;
        float byv = ((float)hh + sy) / (float)HH;
        float bwv = c_biases[2 * a] * expf(tw) / (float)WW;
        float bhv = c_biases[2 * a + 1] * expf(th) / (float)HH;

        bxv = (bxv - (netw - new_w) * 0.5f / netw) / (new_w / netw);
        byv = (byv - (neth - new_h) * 0.5f / neth) / (new_h / neth);
        bwv = bwv * (netw / new_w);
        bhv = bhv * (neth / new_h);

        float cx = bxv * im_w, cy = byv * im_h;
        float bw2 = bwv * im_w, bh2 = bhv * im_h;

        float* bo = bbox + ((size_t)b * NLOC + loc) * 4;
        bo[0] = cx; bo[1] = cy; bo[2] = bw2; bo[3] = bh2;

        float X1 = cx - bw2 * 0.5f, Y1 = cy - bh2 * 0.5f;
        float X2 = cx + bw2 * 0.5f, Y2 = cy + bh2 * 0.5f;
        s->x1[loc] = X1; s->y1[loc] = Y1;
        s->x2[loc] = X2; s->y2[loc] = Y2;
        s->ar[loc] = (X2 - X1) * (Y2 - Y1);

        s->skey[loc] = (obj < PRE_TH) ? 0.0f : obj;
        s->sidx[loc] = loc;
    }
    for (int i = NLOC + tid; i < NPAD; i += NTHR) {
        s->skey[i] = -1.0f;
        s->sidx[i] = NPAD + i;   // larger than any real idx
    }
    for (int w = tid; w < NPAD / 32; w += NTHR) s->kw[w] = 0xFFFFFFFFu;
    if (tid == 0) s->npos = 0;
    __syncthreads();

    // ---- phase 2: bitonic sort, descending by key, ascending idx on ties (stable) ----
    for (unsigned k = 2; k <= NPAD; k <<= 1) {
        for (unsigned j = k >> 1; j > 0; j >>= 1) {
            for (unsigned i = tid; i < NPAD; i += NTHR) {
                unsigned ixj = i ^ j;
                if (ixj > i) {
                    float ka = s->skey[i], kb = s->skey[ixj];
                    int ia = s->sidx[i], ib = s->sidx[ixj];
                    bool b_before_a = (kb > ka) || (kb == ka && ib < ia);
                    bool dirDesc = ((i & k) == 0);
                    if (b_before_a == dirDesc) {
                        s->skey[i] = kb; s->skey[ixj] = ka;
                        s->sidx[i] = ib; s->sidx[ixj] = ia;
                    }
                }
            }
            __syncthreads();
        }
    }

    // count positive scores
    {
        int cnt = 0;
        for (int i = tid; i < NLOC; i += NTHR)
            if (s->skey[i] > 0.0f) cnt++;
        if (cnt) atomicAdd(&s->npos, cnt);
    }
    __syncthreads();
    const int npos = s->npos;

    // ---- phase 3: greedy NMS (iterations == kept boxes only) ----
    int i = 0;
    while (true) {
        if (tid == 0) {
            int found = -1;
            int wd = i >> 5;
            unsigned m0 = s->kw[wd] & (0xFFFFFFFFu << (i & 31));
            while (true) {
                if (m0) {
                    int cand = (wd << 5) + __ffs(m0) - 1;
                    found = (cand < npos) ? cand : -1;
                    break;
                }
                wd++;
                if ((wd << 5) >= npos) { found = -1; break; }
                m0 = s->kw[wd];
            }
            s->nexti = found;
        }
        __syncthreads();
        i = s->nexti;
        if (i < 0) break;

        int oi = s->sidx[i];
        float X1i = s->x1[oi], Y1i = s->y1[oi];
        float X2i = s->x2[oi], Y2i = s->y2[oi];
        float Ai = s->ar[oi];

        for (int j = i + 1 + tid; j < npos; j += NTHR) {
            if ((s->kw[j >> 5] >> (j & 31)) & 1u) {
                int oj = s->sidx[j];
                float iw = fminf(X2i, s->x2[oj]) - fmaxf(X1i, s->x1[oj]);
                float ih = fminf(Y2i, s->y2[oj]) - fmaxf(Y1i, s->y1[oj]);
                iw = fmaxf(iw, 0.0f);
                ih = fmaxf(ih, 0.0f);
                float inter = iw * ih;
                float iou = inter / (Ai + s->ar[oj] - inter + 1e-12f);
                if (iou > NMS_TH)
                    atomicAnd(&s->kw[j >> 5], ~(1u << (j & 31)));
            }
        }
        __syncthreads();
        i++;
    }

    // ---- phase 4: scatter surviving scores into prob channel 20 ----
    for (int p = tid; p < NLOC; p += NTHR) {
        int o = s->sidx[p];
        float v = 0.0f;
        if (s->skey[p] > 0.0f && ((s->kw[p >> 5] >> (p & 31)) & 1u))
            v = s->skey[p];
        prob[((size_t)b * NLOC + o) * 21 + 20] = v;
    }
}

extern "C" void kernel_launch(void* const* d_in, const int* in_sizes, int n_in,
                              void* d_out, int out_size)
{
    (void)in_sizes; (void)n_in; (void)out_size;
    const float* x = (const float*)d_in[0];
    const float* im = (const float*)d_in[1];
    float* out = (float*)d_out;

    cudaFuncSetAttribute(yolo_kernel,
                         cudaFuncAttributeMaxDynamicSharedMemorySize,
                         (int)sizeof(Smem));
    yolo_kernel<<<BATCH, NTHR, sizeof(Smem)>>>(x, im, out);
}

// round 2
// speedup vs baseline: 2.5815x; 2.5815x over previous
#include <cuda_runtime.h>
#include <math.h>

#define NCLS 20
#define NA 5
#define HH 26
#define WW 26
#define NLOC 3380      // NA*HH*WW
#define NPAD 4096
#define NW 106         // ceil(NLOC/32)
#define BATCH 16
#define NMS_TH 0.45f
#define PRE_TH 0.005f
#define FEAT_STRIDE 32.0f

__constant__ float c_biases[10] = {1.08f, 1.19f, 3.42f, 4.41f, 6.63f, 11.38f,
                                   9.42f, 5.11f, 16.62f, 10.52f};

// ---- device scratch (static; no allocations) ----
__device__ float g_x1[BATCH * NLOC], g_y1[BATCH * NLOC];
__device__ float g_x2[BATCH * NLOC], g_y2[BATCH * NLOC];
__device__ float g_ar[BATCH * NLOC], g_score[BATCH * NLOC];
__device__ float g_sx1[BATCH * NLOC], g_sy1[BATCH * NLOC];
__device__ float g_sx2[BATCH * NLOC], g_sy2[BATCH * NLOC];
__device__ float g_sar[BATCH * NLOC], g_ss[BATCH * NLOC];
__device__ int g_sidx[BATCH * NLOC];
__device__ unsigned g_alive[BATCH * NW];
__device__ unsigned g_mat[(size_t)BATCH * NLOC * NW];   // ~22.9 MB

// ============ kernel 1: decode (fully parallel) ============
__global__ void decode_kernel(const float* __restrict__ x,
                              const float* __restrict__ im_info,
                              float* __restrict__ out)
{
    const int b = blockIdx.y;
    const int loc = blockIdx.x * 128 + threadIdx.x;
    if (loc >= NLOC) return;

    const float im_h = im_info[0];
    const float im_w = im_info[1];
    const float netw = WW * FEAT_STRIDE;
    const float neth = HH * FEAT_STRIDE;
    const bool cond = (netw / im_w) < (neth / im_h);
    const float new_w = cond ? netw : im_w * neth / im_h;
    const float new_h = cond ? im_h * netw / im_w : neth;

    float* prob = out;
    float* bbox = out + (size_t)BATCH * NLOC * 21;
    const float* xb = x + (size_t)b * 125 * (HH * WW);

    int a = loc / (HH * WW);
    int rem = loc - a * (HH * WW);
    int hh = rem / WW;
    int ww = rem - hh * WW;

    float tx = xb[(2 * a) * 676 + rem];
    float ty = xb[(2 * a + 1) * 676 + rem];
    float tw = xb[(10 + 2 * a) * 676 + rem];
    float th = xb[(11 + 2 * a) * 676 + rem];
    float to = xb[(20 + a) * 676 + rem];

    float obj = 1.0f / (1.0f + expf(-to));

    float cf[NCLS];
    float m = -INFINITY;
#pragma unroll
    for (int c = 0; c < NCLS; c++) {
        cf[c] = xb[(25 + 5 * c + a) * 676 + rem];
        m = fmaxf(m, cf[c]);
    }
    float sum = 0.0f;
#pragma unroll
    for (int c = 0; c < NCLS; c++) {
        cf[c] = expf(cf[c] - m);
        sum += cf[c];
    }
    float inv = obj / sum;
    float* pr = prob + ((size_t)b * NLOC + loc) * 21;
#pragma unroll
    for (int c = 0; c < NCLS; c++) pr[c] = cf[c] * inv;

    float sx = 1.0f / (1.0f + expf(-tx));
    float sy = 1.0f / (1.0f + expf(-ty));
    float bxv = ((float)ww + sx) / (float)WW;
    float byv = ((float)hh + sy) / (float)HH;
    float bwv = c_biases[2 * a] * expf(tw) / (float)WW;
    float bhv = c_biases[2 * a + 1] * expf(th) / (float)HH;

    bxv = (bxv - (netw - new_w) * 0.5f / netw) / (new_w / netw);
    byv = (byv - (neth - new_h) * 0.5f / neth) / (new_h / neth);
    bwv = bwv * (netw / new_w);
    bhv = bhv * (neth / new_h);

    float cx = bxv * im_w, cy = byv * im_h;
    float bw2 = bwv * im_w, bh2 = bhv * im_h;

    float* bo = bbox + ((size_t)b * NLOC + loc) * 4;
    bo[0] = cx; bo[1] = cy; bo[2] = bw2; bo[3] = bh2;

    float X1 = cx - bw2 * 0.5f, Y1 = cy - bh2 * 0.5f;
    float X2 = cx + bw2 * 0.5f, Y2 = cy + bh2 * 0.5f;
    int gi = b * NLOC + loc;
    g_x1[gi] = X1; g_y1[gi] = Y1;
    g_x2[gi] = X2; g_y2[gi] = Y2;
    g_ar[gi] = (X2 - X1) * (Y2 - Y1);
    g_score[gi] = (obj < PRE_TH) ? 0.0f : obj;
}

// ============ kernel 2: per-batch bitonic sort ============
__global__ void __launch_bounds__(1024, 1)
sort_kernel()
{
    __shared__ float skey[NPAD];
    __shared__ int sidx[NPAD];
    const int b = blockIdx.x;
    const int tid = threadIdx.x;
    const int base = b * NLOC;

    for (int p = tid; p < NLOC; p += 1024) {
        skey[p] = g_score[base + p];
        sidx[p] = p;
    }
    for (int p = NLOC + tid; p < NPAD; p += 1024) {
        skey[p] = -1.0f;
        sidx[p] = NPAD + p;
    }
    __syncthreads();

    for (unsigned k = 2; k <= NPAD; k <<= 1) {
        for (unsigned j = k >> 1; j > 0; j >>= 1) {
            for (unsigned i = tid; i < NPAD; i += 1024) {
                unsigned ixj = i ^ j;
                if (ixj > i) {
                    float ka = skey[i], kb = skey[ixj];
                    int ia = sidx[i], ib = sidx[ixj];
                    bool b_before_a = (kb > ka) || (kb == ka && ib < ia);
                    bool dirDesc = ((i & k) == 0);
                    if (b_before_a == dirDesc) {
                        skey[i] = kb; skey[ixj] = ka;
                        sidx[i] = ib; sidx[ixj] = ia;
                    }
                }
            }
            __syncthreads();
        }
    }

    // gather sorted boxes + emit alive bitmap
    for (int p = tid; p < NLOC; p += 1024) {
        int o = sidx[p];
        g_ss[base + p] = skey[p];
        g_sidx[base + p] = o;
        g_sx1[base + p] = g_x1[base + o];
        g_sy1[base + p] = g_y1[base + o];
        g_sx2[base + p] = g_x2[base + o];
        g_sy2[base + p] = g_y2[base + o];
        g_sar[base + p] = g_ar[base + o];
    }
    __syncthreads();
    for (int chunk = 0; chunk < NPAD; chunk += 1024) {
        int p = chunk + tid;
        bool alive = (p < NLOC) && (skey[p] > 0.0f);
        unsigned w = __ballot_sync(0xFFFFFFFFu, alive);
        int word = p >> 5;
        if ((tid & 31) == 0 && word < NW)
            g_alive[b * NW + word] = w;
    }
}

// ============ kernel 3: pairwise suppression bit-matrix ============
__global__ void mat_kernel()
{
    const int i = blockIdx.x;
    const int b = blockIdx.y;
    const int base = b * NLOC;
    const int lane = threadIdx.x & 31;
    const int warpid = threadIdx.x >> 5;

    const float X1 = g_sx1[base + i], Y1 = g_sy1[base + i];
    const float X2 = g_sx2[base + i], Y2 = g_sy2[base + i];
    const float A  = g_sar[base + i];
    const int fw = i >> 5;

    for (int w = fw + warpid; w < NW; w += 4) {
        int j = w * 32 + lane;
        bool sup = false;
        if (j > i && j < NLOC) {
            float iw = fminf(X2, g_sx2[base + j]) - fmaxf(X1, g_sx1[base + j]);
            float ih = fminf(Y2, g_sy2[base + j]) - fmaxf(Y1, g_sy1[base + j]);
            float inter = fmaxf(iw, 0.0f) * fmaxf(ih, 0.0f);
            // iou > TH  <=>  inter*(1+TH) > TH*(Ai+Aj) + TH*1e-12
            sup = inter * (1.0f + NMS_TH) >
                  NMS_TH * (A + g_sar[base + j]) + NMS_TH * 1e-12f;
        }
        unsigned m = __ballot_sync(0xFFFFFFFFu, sup);
        if (lane == 0)
            g_mat[((size_t)(base + i)) * NW + w] = m;
    }
}

// ============ kernel 4: serial reduction + scatter ============
__global__ void __launch_bounds__(128, 1)
reduce_kernel(float* __restrict__ out)
{
    __shared__ unsigned remv[NW];
    __shared__ unsigned keepm[NW];
    __shared__ unsigned rowbuf[32 * NW];   // 13.5 KB

    const int b = blockIdx.x;
    const int tid = threadIdx.x;
    const int base = b * NLOC;
    const int lane = tid & 31;
    const int warpid = tid >> 5;

    for (int w = tid; w < NW; w += 128) { remv[w] = 0u; keepm[w] = 0u; }
    __syncthreads();

    for (int col = 0; col < NW; col++) {
        int rowlim = NLOC - col * 32;
        if (rowlim > 32) rowlim = 32;

        // stage the 32 candidate rows (words >= col) into smem
        for (int r = warpid; r < rowlim; r += 4) {
            size_t rb = ((size_t)(base + col * 32 + r)) * NW;
            for (int w = col + lane; w < NW; w += 32)
                rowbuf[r * NW + w] = g_mat[rb + w];
        }
        __syncthreads();

        if (tid == 0) {
            unsigned cand = g_alive[b * NW + col] & ~remv[col];
            unsigned kw = 0u;
            while (cand) {
                int bit = __ffs(cand) - 1;
                kw |= 1u << bit;
                cand &= ~(1u << bit);
                cand &= ~rowbuf[bit * NW + col];
            }
            keepm[col] = kw;
        }
        __syncthreads();

        unsigned kw = keepm[col];
        if (kw) {
            for (int w = col + 1 + tid; w < NW; w += 128) {
                unsigned acc = remv[w];
                unsigned kk = kw;
                while (kk) {
                    int bit = __ffs(kk) - 1;
                    kk &= kk - 1;
                    acc |= rowbuf[bit * NW + w];
                }
                remv[w] = acc;
            }
        }
        __syncthreads();
    }

    // scatter surviving scores into prob channel 20
    float* prob = out;
    for (int p = tid; p < NLOC; p += 128) {
        int o = g_sidx[base + p];
        float v = ((keepm[p >> 5] >> (p & 31)) & 1u) ? g_ss[base + p] : 0.0f;
        prob[((size_t)b * NLOC + o) * 21 + 20] = v;
    }
}

extern "C" void kernel_launch(void* const* d_in, const int* in_sizes, int n_in,
                              void* d_out, int out_size)
{
    (void)in_sizes; (void)n_in; (void)out_size;
    const float* x = (const float*)d_in[0];
    const float* im = (const float*)d_in[1];
    float* out = (float*)d_out;

    dim3 g1((NLOC + 127) / 128, BATCH);
    decode_kernel<<<g1, 128>>>(x, im, out);
    sort_kernel<<<BATCH, 1024>>>();
    dim3 g3(NLOC, BATCH);
    mat_kernel<<<g3, 128>>>();
    reduce_kernel<<<BATCH, 128>>>(out);
}

// round 3
// speedup vs baseline: 7.7786x; 3.0133x over previous
#include <cuda_runtime.h>
#include <math.h>

#define NCLS 20
#define NA 5
#define HH 26
#define WW 26
#define NLOC 3380      // NA*HH*WW
#define NPAD 4096
#define NW 106         // ceil(NLOC/32)
#define BATCH 16
#define NMS_TH 0.45f
#define K2 0.31034482758f   // 0.45/1.45
#define PRE_TH 0.005f
#define FEAT_STRIDE 32.0f

__constant__ float c_biases[10] = {1.08f, 1.19f, 3.42f, 4.41f, 6.63f, 11.38f,
                                   9.42f, 5.11f, 16.62f, 10.52f};

// ---- device scratch (static; no allocations) ----
__device__ float g_x1[BATCH * NLOC], g_y1[BATCH * NLOC];
__device__ float g_x2[BATCH * NLOC], g_y2[BATCH * NLOC];
__device__ float g_ka[BATCH * NLOC], g_score[BATCH * NLOC];
__device__ float g_sx1[BATCH * NLOC], g_sy1[BATCH * NLOC];
__device__ float g_sx2[BATCH * NLOC], g_sy2[BATCH * NLOC];
__device__ float g_ska[BATCH * NLOC], g_ss[BATCH * NLOC];
__device__ int g_sidx[BATCH * NLOC];
__device__ unsigned g_alive[BATCH * NW];
// transpose matrix: row j = bitmask over suppressors i (i < j, sorted rank)
__device__ unsigned g_matT[(size_t)BATCH * NLOC * NW];

// ============ kernel 1: decode (fully parallel) ============
__global__ void decode_kernel(const float* __restrict__ x,
                              const float* __restrict__ im_info,
                              float* __restrict__ out)
{
    const int b = blockIdx.y;
    const int loc = blockIdx.x * 128 + threadIdx.x;
    if (loc >= NLOC) return;

    const float im_h = im_info[0];
    const float im_w = im_info[1];
    const float netw = WW * FEAT_STRIDE;
    const float neth = HH * FEAT_STRIDE;
    const bool cond = (netw / im_w) < (neth / im_h);
    const float new_w = cond ? netw : im_w * neth / im_h;
    const float new_h = cond ? im_h * netw / im_w : neth;

    float* prob = out;
    float* bbox = out + (size_t)BATCH * NLOC * 21;
    const float* xb = x + (size_t)b * 125 * (HH * WW);

    int a = loc / (HH * WW);
    int rem = loc - a * (HH * WW);
    int hh = rem / WW;
    int ww = rem - hh * WW;

    float tx = xb[(2 * a) * 676 + rem];
    float ty = xb[(2 * a + 1) * 676 + rem];
    float tw = xb[(10 + 2 * a) * 676 + rem];
    float th = xb[(11 + 2 * a) * 676 + rem];
    float to = xb[(20 + a) * 676 + rem];

    float obj = 1.0f / (1.0f + expf(-to));

    float cf[NCLS];
    float m = -INFINITY;
#pragma unroll
    for (int c = 0; c < NCLS; c++) {
        cf[c] = xb[(25 + 5 * c + a) * 676 + rem];
        m = fmaxf(m, cf[c]);
    }
    float sum = 0.0f;
#pragma unroll
    for (int c = 0; c < NCLS; c++) {
        cf[c] = expf(cf[c] - m);
        sum += cf[c];
    }
    float inv = obj / sum;
    float* pr = prob + ((size_t)b * NLOC + loc) * 21;
#pragma unroll
    for (int c = 0; c < NCLS; c++) pr[c] = cf[c] * inv;

    float sx = 1.0f / (1.0f + expf(-tx));
    float sy = 1.0f / (1.0f + expf(-ty));
    float bxv = ((float)ww + sx) / (float)WW;
    float byv = ((float)hh + sy) / (float)HH;
    float bwv = c_biases[2 * a] * expf(tw) / (float)WW;
    float bhv = c_biases[2 * a + 1] * expf(th) / (float)HH;

    bxv = (bxv - (netw - new_w) * 0.5f / netw) / (new_w / netw);
    byv = (byv - (neth - new_h) * 0.5f / neth) / (new_h / neth);
    bwv = bwv * (netw / new_w);
    bhv = bhv * (neth / new_h);

    float cx = bxv * im_w, cy = byv * im_h;
    float bw2 = bwv * im_w, bh2 = bhv * im_h;

    float* bo = bbox + ((size_t)b * NLOC + loc) * 4;
    bo[0] = cx; bo[1] = cy; bo[2] = bw2; bo[3] = bh2;

    float X1 = cx - bw2 * 0.5f, Y1 = cy - bh2 * 0.5f;
    float X2 = cx + bw2 * 0.5f, Y2 = cy + bh2 * 0.5f;
    int gi = b * NLOC + loc;
    g_x1[gi] = X1; g_y1[gi] = Y1;
    g_x2[gi] = X2; g_y2[gi] = Y2;
    g_ka[gi] = K2 * ((X2 - X1) * (Y2 - Y1));
    g_score[gi] = (obj < PRE_TH) ? 0.0f : obj;
}

// ============ kernel 2: per-batch bitonic sort ============
__global__ void __launch_bounds__(1024, 1)
sort_kernel()
{
    __shared__ float skey[NPAD];
    __shared__ int sidx[NPAD];
    const int b = blockIdx.x;
    const int tid = threadIdx.x;
    const int base = b * NLOC;

    for (int p = tid; p < NLOC; p += 1024) {
        skey[p] = g_score[base + p];
        sidx[p] = p;
    }
    for (int p = NLOC + tid; p < NPAD; p += 1024) {
        skey[p] = -1.0f;
        sidx[p] = NPAD + p;
    }
    __syncthreads();

    for (unsigned k = 2; k <= NPAD; k <<= 1) {
        for (unsigned j = k >> 1; j > 0; j >>= 1) {
            for (unsigned i = tid; i < NPAD; i += 1024) {
                unsigned ixj = i ^ j;
                if (ixj > i) {
                    float ka = skey[i], kb = skey[ixj];
                    int ia = sidx[i], ib = sidx[ixj];
                    bool b_before_a = (kb > ka) || (kb == ka && ib < ia);
                    bool dirDesc = ((i & k) == 0);
                    if (b_before_a == dirDesc) {
                        skey[i] = kb; skey[ixj] = ka;
                        sidx[i] = ib; sidx[ixj] = ia;
                    }
                }
            }
            __syncthreads();
        }
    }

    for (int p = tid; p < NLOC; p += 1024) {
        int o = sidx[p];
        float sc = skey[p];
        g_ss[base + p] = sc;
        g_sidx[base + p] = o;
        g_sx1[base + p] = g_x1[base + o];
        g_sy1[base + p] = g_y1[base + o];
        g_sx2[base + p] = g_x2[base + o];
        g_sy2[base + p] = g_y2[base + o];
        // dead boxes can never suppress: ka = +INF makes inter > kai+kaj false
        g_ska[base + p] = (sc > 0.0f) ? g_ka[base + o] : INFINITY;
    }
    __syncthreads();
    for (int chunk = 0; chunk < NPAD; chunk += 1024) {
        int p = chunk + tid;
        bool alive = (p < NLOC) && (skey[p] > 0.0f);
        unsigned w = __ballot_sync(0xFFFFFFFFu, alive);
        int word = p >> 5;
        if ((tid & 31) == 0 && word < NW)
            g_alive[b * NW + word] = w;
    }
}

// ============ kernel 3: transpose suppression matrix via warp ballot ============
// warp owns i-word w (32 i-boxes in registers); streams j; ballot -> matT[j][w].
__global__ void __launch_bounds__(128, 8)
mat_kernel()
{
    const int w = blockIdx.x;               // i-word index, 0..NW-1
    const int b = blockIdx.z;
    const int base = b * NLOC;
    const int lane = threadIdx.x & 31;
    const int warpid = threadIdx.x >> 5;

    const int i = w * 32 + lane;
    const int iv = (i < NLOC) ? i : (NLOC - 1);
    const float ix1 = g_sx1[base + iv];
    const float iy1 = g_sy1[base + iv];
    const float ix2 = g_sx2[base + iv];
    const float iy2 = g_sy2[base + iv];
    const float ika = (i < NLOC) ? g_ska[base + iv] : INFINITY;

    // j-chunk for this warp
    int cb = blockIdx.y * 1024 + warpid * 256;
    int js = w * 32 + 1; if (cb > js) js = cb;
    int je = cb + 256; if (je > NLOC) je = NLOC;
    if (js >= je) return;

    unsigned* mrow = g_matT + (size_t)base * NW + w;

    for (int j = js; j < je; j++) {
        float jx1 = __ldg(&g_sx1[base + j]);
        float jy1 = __ldg(&g_sy1[base + j]);
        float jx2 = __ldg(&g_sx2[base + j]);
        float jy2 = __ldg(&g_sy2[base + j]);
        float jka = __ldg(&g_ska[base + j]);
        float iw = fminf(ix2, jx2) - fmaxf(ix1, jx1);
        float ih = fminf(iy2, jy2) - fmaxf(iy1, jy1);
        float inter = fmaxf(iw, 0.0f) * fmaxf(ih, 0.0f);
        bool sup = (inter > ika + jka) && (i < j);
        unsigned m = __ballot_sync(0xFFFFFFFFu, sup);
        if (lane == 0)
            mrow[(size_t)j * NW] = m;
    }
}

// ============ kernel 4: parallel fixpoint reduction + scatter ============
__global__ void __launch_bounds__(1024, 1)
reduce_kernel(float* __restrict__ out)
{
    __shared__ unsigned kept[NW];
    __shared__ unsigned removed[NW];
    __shared__ int changed;

    const int b = blockIdx.x;
    const int tid = threadIdx.x;
    const int base = b * NLOC;

    for (int w = tid; w < NW; w += 1024) {
        kept[w] = 0u;
        removed[w] = ~g_alive[b * NW + w];   // dead boxes start removed
    }
    __syncthreads();

    bool det[4];
#pragma unroll
    for (int k = 0; k < 4; k++) {
        int j = tid + k * 1024;
        det[k] = true;
        if (j < NLOC)
            det[k] = ((removed[j >> 5] >> (j & 31)) & 1u) != 0u;  // dead -> done
    }
    __syncthreads();

    while (true) {
        if (tid == 0) changed = 0;
        __syncthreads();

#pragma unroll
        for (int k = 0; k < 4; k++) {
            int j = tid + k * 1024;
            if (j < NLOC && !det[k]) {
                int nwj = (j == 0) ? 0 : (((j - 1) >> 5) + 1);
                const unsigned* row = g_matT + ((size_t)(base + j)) * NW;
                bool anyKept = false, anyAlive = false;
                for (int w = 0; w < nwj; w++) {
                    unsigned v = row[w];
                    if (v) {
                        if (v & kept[w]) { anyKept = true; break; }
                        if (v & ~removed[w]) anyAlive = true;
                    }
                }
                if (anyKept) {
                    atomicOr(&removed[j >> 5], 1u << (j & 31));
                    det[k] = true;
                    changed = 1;
                } else if (!anyAlive) {
                    atomicOr(&kept[j >> 5], 1u << (j & 31));
                    det[k] = true;
                    changed = 1;
                }
            }
        }
        __syncthreads();
        if (!changed) break;
        __syncthreads();
    }

    // scatter surviving scores into prob channel 20
    float* prob = out;
    for (int p = tid; p < NLOC; p += 1024) {
        int o = g_sidx[base + p];
        float sc = g_ss[base + p];
        float v = (sc > 0.0f && ((kept[p >> 5] >> (p & 31)) & 1u)) ? sc : 0.0f;
        prob[((size_t)b * NLOC + o) * 21 + 20] = v;
    }
}

extern "C" void kernel_launch(void* const* d_in, const int* in_sizes, int n_in,
                              void* d_out, int out_size)
{
    (void)in_sizes; (void)n_in; (void)out_size;
    const float* x = (const float*)d_in[0];
    const float* im = (const float*)d_in[1];
    float* out = (float*)d_out;

    dim3 g1((NLOC + 127) / 128, BATCH);
    decode_kernel<<<g1, 128>>>(x, im, out);
    sort_kernel<<<BATCH, 1024>>>();
    dim3 g3(NW, 4, BATCH);
    mat_kernel<<<g3, 128>>>();
    reduce_kernel<<<BATCH, 1024>>>(out);
}

// round 4
// speedup vs baseline: 9.3073x; 1.1965x over previous
#include <cuda_runtime.h>
#include <math.h>

#define NCLS 20
#define NA 5
#define HH 26
#define WW 26
#define NLOC 3380      // NA*HH*WW
#define NPAD 4096
#define NW 106         // ceil(NLOC/32)
#define BATCH 16
#define NMS_TH 0.45f
#define K2 0.31034482758f   // 0.45/1.45
#define PRE_TH 0.005f
#define FEAT_STRIDE 32.0f

__constant__ float c_biases[10] = {1.08f, 1.19f, 3.42f, 4.41f, 6.63f, 11.38f,
                                   9.42f, 5.11f, 16.62f, 10.52f};

// ---- device scratch (static; no allocations) ----
__device__ float g_x1[BATCH * NLOC], g_y1[BATCH * NLOC];
__device__ float g_x2[BATCH * NLOC], g_y2[BATCH * NLOC];
__device__ float g_ka[BATCH * NLOC], g_score[BATCH * NLOC];
__device__ float4 g_sbox[BATCH * NLOC];          // sorted (x1,y1,x2,y2)
__device__ float g_ska[BATCH * NLOC], g_ss[BATCH * NLOC];
__device__ int g_sidx[BATCH * NLOC];
__device__ unsigned g_alive[BATCH * NW];
// transpose matrix: row j = bitmask over suppressors i (i < j, sorted rank)
__device__ unsigned g_matT[(size_t)BATCH * NLOC * NW];

// ============ kernel 1: decode (fully parallel) ============
__global__ void decode_kernel(const float* __restrict__ x,
                              const float* __restrict__ im_info,
                              float* __restrict__ out)
{
    const int b = blockIdx.y;
    const int loc = blockIdx.x * 128 + threadIdx.x;
    if (loc >= NLOC) return;

    const float im_h = im_info[0];
    const float im_w = im_info[1];
    const float netw = WW * FEAT_STRIDE;
    const float neth = HH * FEAT_STRIDE;
    const bool cond = (netw / im_w) < (neth / im_h);
    const float new_w = cond ? netw : im_w * neth / im_h;
    const float new_h = cond ? im_h * netw / im_w : neth;

    float* prob = out;
    float* bbox = out + (size_t)BATCH * NLOC * 21;
    const float* xb = x + (size_t)b * 125 * (HH * WW);

    int a = loc / (HH * WW);
    int rem = loc - a * (HH * WW);
    int hh = rem / WW;
    int ww = rem - hh * WW;

    float tx = xb[(2 * a) * 676 + rem];
    float ty = xb[(2 * a + 1) * 676 + rem];
    float tw = xb[(10 + 2 * a) * 676 + rem];
    float th = xb[(11 + 2 * a) * 676 + rem];
    float to = xb[(20 + a) * 676 + rem];

    float obj = 1.0f / (1.0f + expf(-to));

    float cf[NCLS];
    float m = -INFINITY;
#pragma unroll
    for (int c = 0; c < NCLS; c++) {
        cf[c] = xb[(25 + 5 * c + a) * 676 + rem];
        m = fmaxf(m, cf[c]);
    }
    float sum = 0.0f;
#pragma unroll
    for (int c = 0; c < NCLS; c++) {
        cf[c] = expf(cf[c] - m);
        sum += cf[c];
    }
    float inv = obj / sum;
    float* pr = prob + ((size_t)b * NLOC + loc) * 21;
#pragma unroll
    for (int c = 0; c < NCLS; c++) pr[c] = cf[c] * inv;

    float sx = 1.0f / (1.0f + expf(-tx));
    float sy = 1.0f / (1.0f + expf(-ty));
    float bxv = ((float)ww + sx) / (float)WW;
    float byv = ((float)hh + sy) / (float)HH;
    float bwv = c_biases[2 * a] * expf(tw) / (float)WW;
    float bhv = c_biases[2 * a + 1] * expf(th) / (float)HH;

    bxv = (bxv - (netw - new_w) * 0.5f / netw) / (new_w / netw);
    byv = (byv - (neth - new_h) * 0.5f / neth) / (new_h / neth);
    bwv = bwv * (netw / new_w);
    bhv = bhv * (neth / new_h);

    float cx = bxv * im_w, cy = byv * im_h;
    float bw2 = bwv * im_w, bh2 = bhv * im_h;

    float* bo = bbox + ((size_t)b * NLOC + loc) * 4;
    bo[0] = cx; bo[1] = cy; bo[2] = bw2; bo[3] = bh2;

    float X1 = cx - bw2 * 0.5f, Y1 = cy - bh2 * 0.5f;
    float X2 = cx + bw2 * 0.5f, Y2 = cy + bh2 * 0.5f;
    int gi = b * NLOC + loc;
    g_x1[gi] = X1; g_y1[gi] = Y1;
    g_x2[gi] = X2; g_y2[gi] = Y2;
    g_ka[gi] = K2 * ((X2 - X1) * (Y2 - Y1));
    g_score[gi] = (obj < PRE_TH) ? 0.0f : obj;
}

// ============ kernel 2: per-batch bitonic sort ============
__global__ void __launch_bounds__(1024, 1)
sort_kernel()
{
    __shared__ float skey[NPAD];
    __shared__ int sidx[NPAD];
    const int b = blockIdx.x;
    const int tid = threadIdx.x;
    const int base = b * NLOC;

    for (int p = tid; p < NLOC; p += 1024) {
        skey[p] = g_score[base + p];
        sidx[p] = p;
    }
    for (int p = NLOC + tid; p < NPAD; p += 1024) {
        skey[p] = -1.0f;
        sidx[p] = NPAD + p;
    }
    __syncthreads();

    for (unsigned k = 2; k <= NPAD; k <<= 1) {
        for (unsigned j = k >> 1; j > 0; j >>= 1) {
            for (unsigned i = tid; i < NPAD; i += 1024) {
                unsigned ixj = i ^ j;
                if (ixj > i) {
                    float ka = skey[i], kb = skey[ixj];
                    int ia = sidx[i], ib = sidx[ixj];
                    bool b_before_a = (kb > ka) || (kb == ka && ib < ia);
                    bool dirDesc = ((i & k) == 0);
                    if (b_before_a == dirDesc) {
                        skey[i] = kb; skey[ixj] = ka;
                        sidx[i] = ib; sidx[ixj] = ia;
                    }
                }
            }
            __syncthreads();
        }
    }

    for (int p = tid; p < NLOC; p += 1024) {
        int o = sidx[p];
        float sc = skey[p];
        g_ss[base + p] = sc;
        g_sidx[base + p] = o;
        g_sbox[base + p] = make_float4(g_x1[base + o], g_y1[base + o],
                                       g_x2[base + o], g_y2[base + o]);
        // dead boxes can never suppress: ka = +INF makes inter > kai+kaj false
        g_ska[base + p] = (sc > 0.0f) ? g_ka[base + o] : INFINITY;
    }
    __syncthreads();
    for (int chunk = 0; chunk < NPAD; chunk += 1024) {
        int p = chunk + tid;
        bool alive = (p < NLOC) && (skey[p] > 0.0f);
        unsigned w = __ballot_sync(0xFFFFFFFFu, alive);
        int word = p >> 5;
        if ((tid & 31) == 0 && word < NW)
            g_alive[b * NW + word] = w;
    }
}

// ============ kernel 3: transpose suppression matrix via warp ballot ============
__global__ void __launch_bounds__(128, 8)
mat_kernel()
{
    const int w = blockIdx.x;               // i-word index, 0..NW-1
    const int b = blockIdx.z;
    const int base = b * NLOC;
    const int lane = threadIdx.x & 31;
    const int warpid = threadIdx.x >> 5;

    const int i = w * 32 + lane;
    const int iv = (i < NLOC) ? i : (NLOC - 1);
    const float4 ib = g_sbox[base + iv];
    const float ika = (i < NLOC) ? g_ska[base + iv] : INFINITY;

    int cb = blockIdx.y * 1024 + warpid * 256;
    int js = w * 32 + 1; if (cb > js) js = cb;
    int je = cb + 256; if (je > NLOC) je = NLOC;
    if (js >= je) return;

    unsigned* mrow = g_matT + (size_t)base * NW + w;

#pragma unroll 2
    for (int j = js; j < je; j++) {
        float4 jb = __ldg(&g_sbox[base + j]);
        float jka = __ldg(&g_ska[base + j]);
        float iw = fminf(ib.z, jb.z) - fmaxf(ib.x, jb.x);
        float ih = fminf(ib.w, jb.w) - fmaxf(ib.y, jb.y);
        float inter = fmaxf(iw, 0.0f) * fmaxf(ih, 0.0f);
        bool sup = (inter > ika + jka) && (i < j);
        unsigned m = __ballot_sync(0xFFFFFFFFu, sup);
        if (lane == 0)
            mrow[(size_t)j * NW] = m;
    }
}

// ============ kernel 4: cursor fixpoint reduction + scatter ============
__global__ void __launch_bounds__(1024, 1)
reduce_kernel(float* __restrict__ out)
{
    __shared__ unsigned kept[NW];
    __shared__ unsigned removed[NW];
    __shared__ int changed;

    const int b = blockIdx.x;
    const int tid = threadIdx.x;
    const int base = b * NLOC;

    for (int w = tid; w < NW; w += 1024) {
        kept[w] = 0u;
        removed[w] = ~g_alive[b * NW + w];   // dead boxes start removed
    }
    __syncthreads();

    bool det[4];
    int cw[4];
    unsigned cache[4];

    // ---- init: find first stall word per j (kept==0 now; only removed matters)
#pragma unroll
    for (int k = 0; k < 4; k++) {
        int j = tid + k * 1024;
        det[k] = true;
        cw[k] = 0; cache[k] = 0u;
        if (j >= NLOC) continue;
        if ((removed[j >> 5] >> (j & 31)) & 1u) continue;     // dead -> done
        int nwj = (j == 0) ? 0 : (((j - 1) >> 5) + 1);
        const unsigned* row = g_matT + ((size_t)(base + j)) * NW;
        int stall = -1;
        unsigned sraw = 0u;
        for (int c0 = 0; c0 < nwj && stall < 0; c0 += 16) {
            unsigned vbuf[16];
#pragma unroll
            for (int t = 0; t < 16; t++) {
                int wi = c0 + t;
                vbuf[t] = (wi < nwj) ? __ldg(row + wi) : 0u;
            }
#pragma unroll
            for (int t = 0; t < 16; t++) {
                int wi = c0 + t;
                if (stall < 0 && wi < nwj) {
                    unsigned live = vbuf[t] & ~removed[wi];
                    if (live) { stall = wi; sraw = vbuf[t]; }
                }
            }
        }
        if (stall < 0) {
            atomicOr(&kept[j >> 5], 1u << (j & 31));          // no live suppressors
        } else {
            det[k] = false; cw[k] = stall; cache[k] = sraw;
        }
    }
    __syncthreads();

    // ---- rounds
    while (true) {
        if (tid == 0) changed = 0;
        __syncthreads();

#pragma unroll
        for (int k = 0; k < 4; k++) {
            if (det[k]) continue;
            int j = tid + k * 1024;
            int nwj = ((j - 1) >> 5) + 1;                     // j >= 1 here
            const unsigned* row = g_matT + ((size_t)(base + j)) * NW;

            unsigned raw = cache[k];
            int w = cw[k];
            if (raw & kept[w]) {
                atomicOr(&removed[j >> 5], 1u << (j & 31));
                det[k] = true; changed = 1;
                continue;
            }
            if (raw & ~removed[w]) continue;                  // still stalled

            // stall word cleared: advance
            int stall = -1; unsigned sraw = 0u; bool rem = false;
            for (int c0 = w + 1; c0 < nwj && stall < 0 && !rem; c0 += 8) {
                unsigned vbuf[8];
#pragma unroll
                for (int t = 0; t < 8; t++) {
                    int wi = c0 + t;
                    vbuf[t] = (wi < nwj) ? __ldg(row + wi) : 0u;
                }
#pragma unroll
                for (int t = 0; t < 8; t++) {
                    int wi = c0 + t;
                    if (stall < 0 && !rem && wi < nwj && vbuf[t]) {
                        if (vbuf[t] & kept[wi]) { rem = true; }
                        else if (vbuf[t] & ~removed[wi]) { stall = wi; sraw = vbuf[t]; }
                    }
                }
            }
            if (rem) {
                atomicOr(&removed[j >> 5], 1u << (j & 31));
                det[k] = true; changed = 1;
            } else if (stall < 0) {
                atomicOr(&kept[j >> 5], 1u << (j & 31));
                det[k] = true; changed = 1;
            } else {
                cw[k] = stall; cache[k] = sraw; changed = 1;  // made progress
            }
        }
        __syncthreads();
        if (!changed) break;
        __syncthreads();
    }

    // ---- scatter surviving scores into prob channel 20
    float* prob = out;
    for (int p = tid; p < NLOC; p += 1024) {
        int o = g_sidx[base + p];
        float sc = g_ss[base + p];
        float v = (sc > 0.0f && ((kept[p >> 5] >> (p & 31)) & 1u)) ? sc : 0.0f;
        prob[((size_t)b * NLOC + o) * 21 + 20] = v;
    }
}

extern "C" void kernel_launch(void* const* d_in, const int* in_sizes, int n_in,
                              void* d_out, int out_size)
{
    (void)in_sizes; (void)n_in; (void)out_size;
    const float* x = (const float*)d_in[0];
    const float* im = (const float*)d_in[1];
    float* out = (float*)d_out;

    dim3 g1((NLOC + 127) / 128, BATCH);
    decode_kernel<<<g1, 128>>>(x, im, out);
    sort_kernel<<<BATCH, 1024>>>();
    dim3 g3(NW, 4, BATCH);
    mat_kernel<<<g3, 128>>>();
    reduce_kernel<<<BATCH, 1024>>>(out);
}